// round 3
// baseline (speedup 1.0000x reference)
#include <cuda_runtime.h>
#include <math_constants.h>

#define GRID_SZ 64
#define HALF 2
#define CCH 256
#define KPT 16
#define NB 256
#define KM_TOTAL (256LL * 256LL * 4096LL)

__global__ __launch_bounds__(256, 2)
void pose_kernel(const float* __restrict__ keymap,
                 const float* __restrict__ first_keys,
                 const float* __restrict__ prev_keys,
                 const int*   __restrict__ prev_kps,
                 float* __restrict__ out)
{
    // one block per PAIR of keypoints (same batch b, since 16 kp per b)
    const int bk0  = blockIdx.x * 2;
    const int tid  = threadIdx.x;
    const int lane = tid & 31;
    const int warp = tid >> 5;
    const int h    = tid & 1;     // which float4 half of the 8-float window
    const int cp   = tid >> 1;    // channel pair 0..127
    const int b    = bk0 / KPT;
    const int c0   = 2 * cp;

    int px[2], py[2], a0[2];
    #pragma unroll
    for (int t = 0; t < 2; t++) {
        px[t] = prev_kps[(bk0 + t) * 2 + 0];
        py[t] = prev_kps[(bk0 + t) * 2 + 1];
        a0[t] = (px[t] - HALF) & ~3;     // 16B-aligned window start
    }

    float fk[2][2], pk[2][2];
    #pragma unroll
    for (int t = 0; t < 2; t++) {
        fk[t][0] = first_keys[(bk0 + t) * CCH + c0];
        fk[t][1] = first_keys[(bk0 + t) * CCH + c0 + 1];
        pk[t][0] = prev_keys [(bk0 + t) * CCH + c0];
        pk[t][1] = prev_keys [(bk0 + t) * CCH + c0 + 1];
    }

    float acc[2][5][4];
    #pragma unroll
    for (int t = 0; t < 2; t++)
        #pragma unroll
        for (int i = 0; i < 5; i++)
            #pragma unroll
            for (int w = 0; w < 4; w++)
                acc[t][i][w] = 0.0f;

    // channel-major: both keypoints' rows in the same 16KB plane issued together
    #pragma unroll
    for (int q = 0; q < 2; q++) {
        const long long planeBase = ((long long)(b * CCH + c0 + q)) << 12; // *4096
        #pragma unroll
        for (int t = 0; t < 2; t++) {
            const float fkc = fk[t][q];
            const float pkc = pk[t][q];
            #pragma unroll
            for (int i = 0; i < 5; i++) {
                const int gy = py[t] + i - HALF;
                const bool vy = ((unsigned)gy < GRID_SZ);
                long long idx = planeBase + (long long)(gy * GRID_SZ + a0[t] + 4 * h);
                if (idx < 0) idx = 0;
                if (idx > KM_TOTAL - 4) idx = KM_TOTAL - 4;
                float4 f4 = make_float4(0.f, 0.f, 0.f, 0.f);
                if (vy) f4 = __ldg((const float4*)(keymap + idx));

                float a, d;
                a = f4.x - fkc; d = f4.x - pkc; acc[t][i][0] += 0.25f*a*a + 0.75f*d*d;
                a = f4.y - fkc; d = f4.y - pkc; acc[t][i][1] += 0.25f*a*a + 0.75f*d*d;
                a = f4.z - fkc; d = f4.z - pkc; acc[t][i][2] += 0.25f*a*a + 0.75f*d*d;
                a = f4.w - fkc; d = f4.w - pkc; acc[t][i][3] += 0.25f*a*a + 0.75f*d*d;
            }
        }
    }

    // parity-preserving warp reduction: lane0 keeps h=0 sums, lane1 keeps h=1
    __shared__ float part[8][2][40];
    #pragma unroll
    for (int t = 0; t < 2; t++) {
        #pragma unroll
        for (int i = 0; i < 5; i++) {
            #pragma unroll
            for (int w = 0; w < 4; w++) {
                float v = acc[t][i][w];
                v += __shfl_down_sync(0xFFFFFFFFu, v, 16);
                v += __shfl_down_sync(0xFFFFFFFFu, v, 8);
                v += __shfl_down_sync(0xFFFFFFFFu, v, 4);
                v += __shfl_down_sync(0xFFFFFFFFu, v, 2);
                if (lane < 2) part[warp][lane][t * 20 + i * 4 + w] = v;
            }
        }
    }
    __syncthreads();

    __shared__ float dmap[2][25];
    if (tid < 50) {
        const int t    = tid / 25;
        const int cell = tid % 25;
        const int i = cell / 5;
        const int j = cell % 5;
        const int pxt = px[t], pyt = py[t];
        const int r  = (pxt - HALF) - a0[t];   // 0..3
        const int w    = r + j;                // 0..7
        const int wh   = w >> 2;
        const int slot = t * 20 + i * 4 + (w & 3);
        float s = 0.0f;
        #pragma unroll
        for (int wp = 0; wp < 8; wp++) s += part[wp][wh][slot];

        const int gx = pxt + j - HALF;
        const int gy = pyt + i - HALF;
        const bool valid = ((unsigned)gx < GRID_SZ) && ((unsigned)gy < GRID_SZ);

        // weight map (window-local coords, replicating reference)
        const int x0 = max(pxt - HALF, 0);
        const int y0 = max(pyt - HALF, 0);
        const int Wd = min(pxt + HALF, GRID_SZ - 1) - x0 + 1;
        const int Hd = min(pyt + HALF, GRID_SZ - 1) - y0 + 1;
        const int tx = pxt - x0, ty = pyt - y0;
        const int wx = gx - x0,  wy = gy - y0;

        const int xl1 = max(tx - 1, 0), xr1 = min(tx + 1, Wd - 1);
        const int yu1 = max(ty - 1, 0), yd1 = min(ty + 1, Hd - 1);
        const bool in_x1 = (wx >= xl1) && (wx <= xr1);
        const bool in_y1 = (wy >= yu1) && (wy <= yd1);
        const bool ring1 = (((wx == xl1) || (wx == xr1)) && in_y1) ||
                           (((wy == yu1) || (wy == yd1)) && in_x1);
        float wgt = ring1 ? 0.6f : 0.5f;

        const int xl2 = max(tx - 2, 0), xr2 = min(tx + 2, Wd - 1);
        const int yu2 = max(ty - 2, 0), yd2 = min(ty + 2, Hd - 1);
        const bool in_x2 = (wx >= xl2) && (wx <= xr2);
        const bool in_y2 = (wy >= yu2) && (wy <= yd2);
        const bool l_skip = (xl1 == 0), r_skip = (xr1 == Wd - 1);
        const bool u_skip = (yu1 == 0), d_skip = (yd1 == Hd - 1);
        const bool ring2 = (!l_skip && (wx == xl2) && in_y2) ||
                           (!r_skip && (wx == xr2) && in_y2) ||
                           (!u_skip && (wy == yu2) && in_x2) ||
                           (!d_skip && (wy == yd2) && in_x2);
        if (ring2) wgt = 0.7f;

        dmap[t][cell] = valid ? (wgt * s) : CUDART_INF_F;
    }
    __syncthreads();

    if (tid < 2) {
        const int t = tid;
        float best = dmap[t][0];
        int bi = 0;
        #pragma unroll
        for (int i = 1; i < 25; i++) {
            const float v = dmap[t][i];
            if (v < best) { best = v; bi = i; }
        }
        const int ox = bi % 5 - HALF;
        const int oy = bi / 5 - HALF;
        const int bk = bk0 + t;
        out[bk * 2 + 0] = (float)(px[t] + ox);
        out[bk * 2 + 1] = (float)(py[t] + oy);
        out[NB * KPT * 2 + bk] = best;
    }
}

extern "C" void kernel_launch(void* const* d_in, const int* in_sizes, int n_in,
                              void* d_out, int out_size)
{
    const float* keymap     = (const float*)d_in[0];
    const float* first_keys = (const float*)d_in[1];
    const float* prev_keys  = (const float*)d_in[2];
    const int*   prev_kps   = (const int*)d_in[3];
    float* out = (float*)d_out;

    pose_kernel<<<NB * KPT / 2, 256>>>(keymap, first_keys, prev_keys, prev_kps, out);
}

// round 4
// speedup vs baseline: 1.0171x; 1.0171x over previous
#include <cuda_runtime.h>
#include <math_constants.h>

#define GRID_SZ 64
#define HALF 2
#define CCH 256
#define KPT 16
#define NB 256
#define KM_TOTAL_I (256 * 256 * 4096)   // 2^28 floats, fits int32

__global__ __launch_bounds__(256, 4)
void pose_kernel(const float* __restrict__ keymap,
                 const float* __restrict__ first_keys,
                 const float* __restrict__ prev_keys,
                 const int*   __restrict__ prev_kps,
                 float* __restrict__ out)
{
    // one block per (b,k)
    const int bk   = blockIdx.x;
    const int tid  = threadIdx.x;
    const int lane = tid & 31;
    const int warp = tid >> 5;
    const int h    = tid & 1;     // which float4 half of the 8-float window
    const int cp   = tid >> 1;    // channel pair 0..127
    const int b    = bk >> 4;     // bk / KPT

    const int px = prev_kps[bk * 2 + 0];
    const int py = prev_kps[bk * 2 + 1];

    // 16B-aligned 8-float region [a0, a0+8) covers window cols [px-2, px+2]
    const int a0 = (px - HALF) & ~3;

    const int c0 = 2 * cp;
    const float fk0 = first_keys[bk * CCH + c0];
    const float fk1 = first_keys[bk * CCH + c0 + 1];
    const float pk0 = prev_keys [bk * CCH + c0];
    const float pk1 = prev_keys [bk * CCH + c0 + 1];

    // per-row offsets within a plane (int32), clamped later with plane base
    int rowOff[5];
    bool vy[5];
    #pragma unroll
    for (int i = 0; i < 5; i++) {
        const int gy = py + i - HALF;
        vy[i] = ((unsigned)gy < GRID_SZ);
        rowOff[i] = gy * GRID_SZ + a0 + 4 * h;
    }

    const int planeBase0 = (b * CCH + c0) << 12;       // * 4096

    float acc[5][4];
    #pragma unroll
    for (int i = 0; i < 5; i++)
        #pragma unroll
        for (int w = 0; w < 4; w++)
            acc[i][w] = 0.0f;

    #pragma unroll
    for (int q = 0; q < 2; q++) {
        const float fk = q ? fk1 : fk0;
        const float pk = q ? pk1 : pk0;
        const int planeBase = planeBase0 + (q << 12);
        #pragma unroll
        for (int i = 0; i < 5; i++) {
            int idx = planeBase + rowOff[i];
            idx = max(idx, 0);
            idx = min(idx, KM_TOTAL_I - 4);
            float4 f4 = make_float4(0.f, 0.f, 0.f, 0.f);
            if (vy[i]) f4 = __ldg((const float4*)(keymap + idx));

            float a, d;
            a = f4.x - fk; d = f4.x - pk; acc[i][0] += 0.25f*a*a + 0.75f*d*d;
            a = f4.y - fk; d = f4.y - pk; acc[i][1] += 0.25f*a*a + 0.75f*d*d;
            a = f4.z - fk; d = f4.z - pk; acc[i][2] += 0.25f*a*a + 0.75f*d*d;
            a = f4.w - fk; d = f4.w - pk; acc[i][3] += 0.25f*a*a + 0.75f*d*d;
        }
    }

    // parity-preserving warp reduction: lane0 keeps h=0 sums, lane1 keeps h=1
    __shared__ float part[8][2][20];
    #pragma unroll
    for (int i = 0; i < 5; i++) {
        #pragma unroll
        for (int w = 0; w < 4; w++) {
            float v = acc[i][w];
            v += __shfl_down_sync(0xFFFFFFFFu, v, 16);
            v += __shfl_down_sync(0xFFFFFFFFu, v, 8);
            v += __shfl_down_sync(0xFFFFFFFFu, v, 4);
            v += __shfl_down_sync(0xFFFFFFFFu, v, 2);
            if (lane < 2) part[warp][lane][i * 4 + w] = v;
        }
    }
    __syncthreads();

    __shared__ float dmap[25];
    if (tid < 25) {
        const int i = tid / 5;
        const int j = tid % 5;
        const int r    = (px - HALF) - a0;   // 0..3
        const int w    = r + j;              // 0..7
        const int wh   = w >> 2;
        const int slot = i * 4 + (w & 3);
        float s = 0.0f;
        #pragma unroll
        for (int wp = 0; wp < 8; wp++) s += part[wp][wh][slot];

        const int gx = px + j - HALF;
        const int gy = py + i - HALF;
        const bool valid = ((unsigned)gx < GRID_SZ) && ((unsigned)gy < GRID_SZ);

        // weight map (window-local coords, replicating reference)
        const int x0 = max(px - HALF, 0);
        const int y0 = max(py - HALF, 0);
        const int Wd = min(px + HALF, GRID_SZ - 1) - x0 + 1;
        const int Hd = min(py + HALF, GRID_SZ - 1) - y0 + 1;
        const int tx = px - x0, ty = py - y0;
        const int wx = gx - x0, wy = gy - y0;

        const int xl1 = max(tx - 1, 0), xr1 = min(tx + 1, Wd - 1);
        const int yu1 = max(ty - 1, 0), yd1 = min(ty + 1, Hd - 1);
        const bool in_x1 = (wx >= xl1) && (wx <= xr1);
        const bool in_y1 = (wy >= yu1) && (wy <= yd1);
        const bool ring1 = (((wx == xl1) || (wx == xr1)) && in_y1) ||
                           (((wy == yu1) || (wy == yd1)) && in_x1);
        float wgt = ring1 ? 0.6f : 0.5f;

        const int xl2 = max(tx - 2, 0), xr2 = min(tx + 2, Wd - 1);
        const int yu2 = max(ty - 2, 0), yd2 = min(ty + 2, Hd - 1);
        const bool in_x2 = (wx >= xl2) && (wx <= xr2);
        const bool in_y2 = (wy >= yu2) && (wy <= yd2);
        const bool l_skip = (xl1 == 0), r_skip = (xr1 == Wd - 1);
        const bool u_skip = (yu1 == 0), d_skip = (yd1 == Hd - 1);
        const bool ring2 = (!l_skip && (wx == xl2) && in_y2) ||
                           (!r_skip && (wx == xr2) && in_y2) ||
                           (!u_skip && (wy == yu2) && in_x2) ||
                           (!d_skip && (wy == yd2) && in_x2);
        if (ring2) wgt = 0.7f;

        dmap[tid] = valid ? (wgt * s) : CUDART_INF_F;
    }
    __syncthreads();

    if (tid == 0) {
        float best = dmap[0];
        int bi = 0;
        #pragma unroll
        for (int i = 1; i < 25; i++) {
            const float v = dmap[i];
            if (v < best) { best = v; bi = i; }
        }
        const int ox = bi % 5 - HALF;
        const int oy = bi / 5 - HALF;
        out[bk * 2 + 0] = (float)(px + ox);
        out[bk * 2 + 1] = (float)(py + oy);
        out[NB * KPT * 2 + bk] = best;
    }
}

extern "C" void kernel_launch(void* const* d_in, const int* in_sizes, int n_in,
                              void* d_out, int out_size)
{
    const float* keymap     = (const float*)d_in[0];
    const float* first_keys = (const float*)d_in[1];
    const float* prev_keys  = (const float*)d_in[2];
    const int*   prev_kps   = (const int*)d_in[3];
    float* out = (float*)d_out;

    pose_kernel<<<NB * KPT, 256>>>(keymap, first_keys, prev_keys, prev_kps, out);
}

// round 5
// speedup vs baseline: 1.0174x; 1.0004x over previous
#include <cuda_runtime.h>
#include <math_constants.h>

#define GRID_SZ 64
#define HALF 2
#define CCH 256
#define KPT 16
#define NB 256
#define KM_TOTAL_I (256 * 256 * 4096)   // 2^28 floats, fits int32

__global__ __launch_bounds__(256, 4)
void pose_kernel(const float* __restrict__ keymap,
                 const float* __restrict__ first_keys,
                 const float* __restrict__ prev_keys,
                 const int*   __restrict__ prev_kps,
                 float* __restrict__ out)
{
    // one block per (b,k)
    const int bk   = blockIdx.x;
    const int tid  = threadIdx.x;
    const int lane = tid & 31;
    const int warp = tid >> 5;
    const int h    = tid & 1;     // which float4 half of the 8-float window
    const int cp   = tid >> 1;    // channel pair 0..127
    const int b    = bk >> 4;

    const int px = prev_kps[bk * 2 + 0];
    const int py = prev_kps[bk * 2 + 1];

    // 16B-aligned 8-float region [a0, a0+8) covers window cols [px-2, px+2]
    const int a0 = (px - HALF) & ~3;

    const int c0 = 2 * cp;
    const float fk0 = first_keys[bk * CCH + c0];
    const float fk1 = first_keys[bk * CCH + c0 + 1];
    const float pk0 = prev_keys [bk * CCH + c0];
    const float pk1 = prev_keys [bk * CCH + c0 + 1];

    const int planeBase0 = (b * CCH + c0) << 12;   // * 4096

    // ---- batch ALL 10 LDG.128 before any math ----
    float4 f[10];
    #pragma unroll
    for (int n = 0; n < 10; n++) {
        const int q = n >= 5;            // channel within pair
        const int i = n - 5 * q;         // window row
        const int gy = py + i - HALF;
        const bool vy = ((unsigned)gy < GRID_SZ);
        int idx = planeBase0 + (q << 12) + gy * GRID_SZ + a0 + 4 * h;
        idx = max(idx, 0);
        idx = min(idx, KM_TOTAL_I - 4);
        f[n] = make_float4(0.f, 0.f, 0.f, 0.f);
        if (vy) f[n] = __ldg((const float4*)(keymap + idx));
    }

    // ---- consume into 20 accumulators ----
    float acc[5][4];
    #pragma unroll
    for (int i = 0; i < 5; i++) {
        const float4 u = f[i];       // q=0
        const float4 v = f[i + 5];   // q=1
        float a, d;
        a = u.x - fk0; d = u.x - pk0; acc[i][0]  = 0.25f*a*a + 0.75f*d*d;
        a = u.y - fk0; d = u.y - pk0; acc[i][1]  = 0.25f*a*a + 0.75f*d*d;
        a = u.z - fk0; d = u.z - pk0; acc[i][2]  = 0.25f*a*a + 0.75f*d*d;
        a = u.w - fk0; d = u.w - pk0; acc[i][3]  = 0.25f*a*a + 0.75f*d*d;
        a = v.x - fk1; d = v.x - pk1; acc[i][0] += 0.25f*a*a + 0.75f*d*d;
        a = v.y - fk1; d = v.y - pk1; acc[i][1] += 0.25f*a*a + 0.75f*d*d;
        a = v.z - fk1; d = v.z - pk1; acc[i][2] += 0.25f*a*a + 0.75f*d*d;
        a = v.w - fk1; d = v.w - pk1; acc[i][3] += 0.25f*a*a + 0.75f*d*d;
    }

    // parity-preserving warp reduction: lane0 keeps h=0 sums, lane1 keeps h=1
    __shared__ float part[8][2][20];
    #pragma unroll
    for (int i = 0; i < 5; i++) {
        #pragma unroll
        for (int w = 0; w < 4; w++) {
            float v = acc[i][w];
            v += __shfl_down_sync(0xFFFFFFFFu, v, 16);
            v += __shfl_down_sync(0xFFFFFFFFu, v, 8);
            v += __shfl_down_sync(0xFFFFFFFFu, v, 4);
            v += __shfl_down_sync(0xFFFFFFFFu, v, 2);
            if (lane < 2) part[warp][lane][i * 4 + w] = v;
        }
    }
    __syncthreads();

    __shared__ float dmap[25];
    if (tid < 25) {
        const int i = tid / 5;
        const int j = tid % 5;
        const int r    = (px - HALF) - a0;   // 0..3
        const int w    = r + j;              // 0..7
        const int wh   = w >> 2;
        const int slot = i * 4 + (w & 3);
        float s = 0.0f;
        #pragma unroll
        for (int wp = 0; wp < 8; wp++) s += part[wp][wh][slot];

        const int gx = px + j - HALF;
        const int gy = py + i - HALF;
        const bool valid = ((unsigned)gx < GRID_SZ) && ((unsigned)gy < GRID_SZ);

        // weight map (window-local coords, replicating reference)
        const int x0 = max(px - HALF, 0);
        const int y0 = max(py - HALF, 0);
        const int Wd = min(px + HALF, GRID_SZ - 1) - x0 + 1;
        const int Hd = min(py + HALF, GRID_SZ - 1) - y0 + 1;
        const int tx = px - x0, ty = py - y0;
        const int wx = gx - x0, wy = gy - y0;

        const int xl1 = max(tx - 1, 0), xr1 = min(tx + 1, Wd - 1);
        const int yu1 = max(ty - 1, 0), yd1 = min(ty + 1, Hd - 1);
        const bool in_x1 = (wx >= xl1) && (wx <= xr1);
        const bool in_y1 = (wy >= yu1) && (wy <= yd1);
        const bool ring1 = (((wx == xl1) || (wx == xr1)) && in_y1) ||
                           (((wy == yu1) || (wy == yd1)) && in_x1);
        float wgt = ring1 ? 0.6f : 0.5f;

        const int xl2 = max(tx - 2, 0), xr2 = min(tx + 2, Wd - 1);
        const int yu2 = max(ty - 2, 0), yd2 = min(ty + 2, Hd - 1);
        const bool in_x2 = (wx >= xl2) && (wx <= xr2);
        const bool in_y2 = (wy >= yu2) && (wy <= yd2);
        const bool l_skip = (xl1 == 0), r_skip = (xr1 == Wd - 1);
        const bool u_skip = (yu1 == 0), d_skip = (yd1 == Hd - 1);
        const bool ring2 = (!l_skip && (wx == xl2) && in_y2) ||
                           (!r_skip && (wx == xr2) && in_y2) ||
                           (!u_skip && (wy == yu2) && in_x2) ||
                           (!d_skip && (wy == yd2) && in_x2);
        if (ring2) wgt = 0.7f;

        dmap[tid] = valid ? (wgt * s) : CUDART_INF_F;
    }
    __syncthreads();

    if (tid == 0) {
        float best = dmap[0];
        int bi = 0;
        #pragma unroll
        for (int i = 1; i < 25; i++) {
            const float v = dmap[i];
            if (v < best) { best = v; bi = i; }
        }
        const int ox = bi % 5 - HALF;
        const int oy = bi / 5 - HALF;
        out[bk * 2 + 0] = (float)(px + ox);
        out[bk * 2 + 1] = (float)(py + oy);
        out[NB * KPT * 2 + bk] = best;
    }
}

extern "C" void kernel_launch(void* const* d_in, const int* in_sizes, int n_in,
                              void* d_out, int out_size)
{
    const float* keymap     = (const float*)d_in[0];
    const float* first_keys = (const float*)d_in[1];
    const float* prev_keys  = (const float*)d_in[2];
    const int*   prev_kps   = (const int*)d_in[3];
    float* out = (float*)d_out;

    pose_kernel<<<NB * KPT, 256>>>(keymap, first_keys, prev_keys, prev_kps, out);
}